// round 16
// baseline (speedup 1.0000x reference)
#include <cuda_runtime.h>
#include <math.h>

#define T_LEN  2000
#define FC     514            // 257 * 2
#define NSER   8224           // 16 * 514
#define NPAIRS (NSER / 2)     // 4112 float2 series-pairs
#define HPAIRS (NPAIRS / 2)   // 2056 -- pass1 threads (2 pairs each)
#define FC2    (FC / 2)       // 257 pairs per row
#define CH     40             // number of time chunks (R12-proven best)
#define LCH    50             // chunk length
#define NBX1   9              // ceil(HPAIRS / 256) -- pass1 grid x
#define NBX2   17             // ceil(NPAIRS / 256) -- pass2 grid x

// All data-independent constants, computed on the HOST.
struct CoefTab {
    float4 c4[T_LEN];   // per-t: (w, a = 1-w, b = w*a, bP = b * Ppre_u)
    float2 ck[CH];      // per-chunk: (P, gamma)
};
__constant__ CoefTab g_ct;

// Per (chunk, series) scratch.
__device__ float g_q [CH * NSER];
__device__ float g_al[CH * NSER];
__device__ float g_be[CH * NSER];
__device__ float g_v2[CH * NSER];
__device__ float g_s [CH * NSER];
// Completion counters per x-slice; combiner self-resets -> graph-replay safe.
__device__ int g_cnt[NBX1];

// Kernel 1: pass1 -- TWO series-pairs per thread (independent LDG/FMA chains)
// + last-block combine tail.
__global__ __launch_bounds__(256)
void pass1_kernel(const float* __restrict__ in) {
    __shared__ int sflag;
    int c  = blockIdx.y;
    int pr = blockIdx.x * 256 + threadIdx.x;     // 0..2303
    bool act = (pr < HPAIRS);
    const float4* cf = g_ct.c4 + c * LCH;
    int prA = pr, prB = pr + HPAIRS;

    if (act) {
        int nA = prA / FC2, fA = prA - nA * FC2;
        int nB = prB / FC2, fB = prB - nB * FC2;
        const float2* xpA = (const float2*)in
            + ((size_t)nA * T_LEN + (size_t)c * LCH) * FC2 + fA;
        const float2* xpB = (const float2*)in
            + ((size_t)nB * T_LEN + (size_t)c * LCH) * FC2 + fB;

        float QA0=0.f,QA1=0.f,aA0=0.f,aA1=0.f,bA0=0.f,bA1=0.f;
        float QB0=0.f,QB1=0.f,aB0=0.f,aB1=0.f,bB0=0.f,bB1=0.f;
#pragma unroll 10
        for (int u = 0; u < LCH; u++) {
            float4 k  = cf[u];                   // constant cache broadcast
            float2 xA = __ldg(xpA + (size_t)u * FC2);
            float2 xB = __ldg(xpB + (size_t)u * FC2);
            float uA0 = xA.x - QA0, uA1 = xA.y - QA1;
            float uB0 = xB.x - QB0, uB1 = xB.y - QB1;
            QA0 = fmaf(k.x, uA0, QA0);  QA1 = fmaf(k.x, uA1, QA1);
            QB0 = fmaf(k.x, uB0, QB0);  QB1 = fmaf(k.x, uB1, QB1);
            aA0 = fmaf(k.y, aA0, (k.z * uA0) * uA0);
            aA1 = fmaf(k.y, aA1, (k.z * uA1) * uA1);
            aB0 = fmaf(k.y, aB0, (k.z * uB0) * uB0);
            aB1 = fmaf(k.y, aB1, (k.z * uB1) * uB1);
            bA0 = fmaf(k.y, bA0, k.w * uA0);
            bA1 = fmaf(k.y, bA1, k.w * uA1);
            bB0 = fmaf(k.y, bB0, k.w * uB0);
            bB1 = fmaf(k.y, bB1, k.w * uB1);
        }
        int iA = c * NSER + prA * 2;
        int iB = c * NSER + prB * 2;
        *(float2*)&g_q [iA] = make_float2(QA0, QA1);
        *(float2*)&g_al[iA] = make_float2(aA0, aA1);
        *(float2*)&g_be[iA] = make_float2(bA0, bA1);
        *(float2*)&g_q [iB] = make_float2(QB0, QB1);
        *(float2*)&g_al[iB] = make_float2(aB0, aB1);
        *(float2*)&g_be[iB] = make_float2(bB0, bB1);
    }

    // Arrive: one acq_rel atomic per block publishes the block's stores.
    __syncthreads();
    if (threadIdx.x == 0) {
        int old;
        asm volatile("atom.add.acq_rel.gpu.global.s32 %0, [%1], 1;"
                     : "=r"(old) : "l"(&g_cnt[blockIdx.x]) : "memory");
        sflag = (old == CH - 1);
    }
    __syncthreads();
    if (!sflag) return;

    // Last-arriving block of this x-slice combines BOTH its pairs.
    if (act) {
        float vA0=0.f,vA1=0.f,SA0=0.f,SA1=0.f;
        float vB0=0.f,vB1=0.f,SB0=0.f,SB1=0.f;
#pragma unroll 8
        for (int k = 0; k < CH; k++) {
            float2 pg = g_ct.ck[k];              // (P, gamma)
            int iA = k * NSER + prA * 2;
            int iB = k * NSER + prB * 2;
            float2 qA  = __ldcg((const float2*)&g_q [iA]);
            float2 alA = __ldcg((const float2*)&g_al[iA]);
            float2 beA = __ldcg((const float2*)&g_be[iA]);
            float2 qB  = __ldcg((const float2*)&g_q [iB]);
            float2 alB = __ldcg((const float2*)&g_al[iB]);
            float2 beB = __ldcg((const float2*)&g_be[iB]);
            *(float2*)&g_v2[iA] = make_float2(vA0, vA1);
            *(float2*)&g_s [iA] = make_float2(SA0, SA1);
            *(float2*)&g_v2[iB] = make_float2(vB0, vB1);
            *(float2*)&g_s [iB] = make_float2(SB0, SB1);
            // S' = P*S + al + v2*(gamma*v2 - 2*be);  v2' = P*v2 + Q
            float cA0 = fmaf(pg.y, vA0, -2.0f * beA.x);
            float cA1 = fmaf(pg.y, vA1, -2.0f * beA.y);
            float cB0 = fmaf(pg.y, vB0, -2.0f * beB.x);
            float cB1 = fmaf(pg.y, vB1, -2.0f * beB.y);
            SA0 = fmaf(pg.x, SA0, fmaf(vA0, cA0, alA.x));
            SA1 = fmaf(pg.x, SA1, fmaf(vA1, cA1, alA.y));
            SB0 = fmaf(pg.x, SB0, fmaf(vB0, cB0, alB.x));
            SB1 = fmaf(pg.x, SB1, fmaf(vB1, cB1, alB.y));
            vA0 = fmaf(pg.x, vA0, qA.x);  vA1 = fmaf(pg.x, vA1, qA.y);
            vB0 = fmaf(pg.x, vB0, qB.x);  vB1 = fmaf(pg.x, vB1, qB.y);
        }
    }
    // Self-reset for the next (graph-replayed) launch.
    if (threadIdx.x == 0) g_cnt[blockIdx.x] = 0;
}

// Kernel 2: pass2 — replay each chunk with exact start state (R12-proven).
__global__ __launch_bounds__(256)
void pass2_kernel(const float* __restrict__ in, float* __restrict__ out) {
    int pr = blockIdx.x * 256 + threadIdx.x;
    int c  = blockIdx.y;
    if (pr >= NPAIRS) return;
    int n  = pr / FC2;
    int fp = pr - n * FC2;
    size_t base = ((size_t)n * T_LEN + (size_t)c * LCH) * FC2 + fp;
    const float2* xp = (const float2*)in  + base;
    float2*       yp = (float2*)out + base;
    const float4* cf = g_ct.c4 + c * LCH;

    int idx = c * NSER + pr * 2;
    float2 v2 = __ldg((const float2*)&g_v2[idx]);
    float2 S  = __ldg((const float2*)&g_s [idx]);
    float v20 = v2.x, v21 = v2.y, S0 = S.x, S1 = S.y;

#pragma unroll 10
    for (int u = 0; u < LCH; u++) {
        float4 k = cf[u];                        // constant cache broadcast
        float2 x = __ldg(xp + (size_t)u * FC2);
        float d0 = x.x - v20;
        float d1 = x.y - v21;
        v20 = fmaf(k.x, d0, v20);
        v21 = fmaf(k.x, d1, v21);
        S0 = fmaf(k.y, S0, (k.z * d0) * d0);
        S1 = fmaf(k.y, S1, (k.z * d1) * d1);
        float r0 = rsqrtf(fmaxf(S0, 0.0f) + 1e-5f);
        float r1 = rsqrtf(fmaxf(S1, 0.0f) + 1e-5f);
        float2 y;
        y.x = (k.y * d0) * r0;
        y.y = (k.y * d1) * r1;
        __stcs(yp + (size_t)u * FC2, y);
    }
}

// Static host-side coefficient table: stays valid across graph replays.
static CoefTab h_ct;

static void fill_coefs_host() {
    const double b  = (double)0.99f;
    const double c1 = (double)(1.0f - 0.99f);   // exact (Sterbenz)
    for (int t = 0; t < T_LEN; t++) {
        int u  = t % LCH;
        int t0 = t - u;
        double bt1 = pow(b, (double)(t + 1));
        double w   = c1 / (1.0 - bt1);          // w_0 == 1 exactly
        double a   = 1.0 - w;
        double bb  = w * a;
        double Ppre = (u == 0) ? 1.0
                    : pow(b, (double)u) * (1.0 - pow(b, (double)t0))
                      / (1.0 - pow(b, (double)t));
        h_ct.c4[t] = make_float4((float)w, (float)a, (float)bb,
                                 (float)(bb * Ppre));
    }
    for (int c = 0; c < CH; c++) {
        int t0 = c * LCH;
        double ratio = (1.0 - pow(b, (double)t0))
                     / (1.0 - pow(b, (double)(t0 + LCH)));
        double P     = pow(b, (double)LCH) * ratio;   // 0 for chunk 0
        double ga    = (c == 0) ? 0.0
                     : (P / pow(b, (double)t0)) * (1.0 - ratio);
        h_ct.ck[c] = make_float2((float)P, (float)ga);
    }
}

extern "C" void kernel_launch(void* const* d_in, const int* in_sizes, int n_in,
                              void* d_out, int out_size) {
    const float* s = (const float*)d_in[0];
    float* out = (float*)d_out;
    fill_coefs_host();   // same values every call -> deterministic
    cudaMemcpyToSymbolAsync(g_ct, &h_ct, sizeof(CoefTab), 0,
                            cudaMemcpyHostToDevice);
    pass1_kernel<<<dim3(NBX1, CH), 256>>>(s);        // (9, 40), 2 pairs/thread
    pass2_kernel<<<dim3(NBX2, CH), 256>>>(s, out);   // (17, 40)
}

// round 17
// speedup vs baseline: 1.0860x; 1.0860x over previous
#include <cuda_runtime.h>
#include <math.h>

#define T_LEN  2000
#define FC     514            // 257 * 2
#define NSER   8224           // 16 * 514
#define NPAIRS (NSER / 2)     // 4112 float2 series-pairs
#define FC2    (FC / 2)       // 257 pairs per row
#define CH     40             // number of time chunks (R12-proven best)
#define LCH    50             // chunk length
#define NBX    17             // ceil(NPAIRS / 256)

// All data-independent constants, computed on the HOST.
struct CoefTab {
    float4 c4[T_LEN];   // per-t: (w, a = 1-w, b = w*a, bP = b * Ppre_u)
    float2 ck[CH];      // per-chunk: (P, gamma)
};
__constant__ CoefTab g_ct;

// Per (chunk, series) scratch.
__device__ float g_q [CH * NSER];
__device__ float g_al[CH * NSER];
__device__ float g_be[CH * NSER];
__device__ float g_v2[CH * NSER];
__device__ float g_s [CH * NSER];
// Per x-slice sync state. All self-reset each launch -> graph-replay safe.
__device__ int g_cnt [NBX];   // pass1 arrivals  (combiner resets)
__device__ int g_rcnt[NBX];   // pass2 readers   (last reader resets)
__device__ int g_done[NBX];   // slice combine-done flag (last reader resets)

__device__ __forceinline__ int ld_acq(const int* p) {
    int v;
    asm volatile("ld.acquire.gpu.global.b32 %0, [%1];"
                 : "=r"(v) : "l"(p) : "memory");
    return v;
}
__device__ __forceinline__ void st_rel(int* p, int v) {
    asm volatile("st.release.gpu.global.b32 [%0], %1;"
                 :: "l"(p), "r"(v) : "memory");
}

// Fused launch: grid (NBX, 2*CH).
//   y <  CH : pass1 for chunk y (+ last-block combine, sets slice flag)
//   y >= CH : pass2 for chunk y-CH (single-hop wait on slice flag)
// Blocks dispatch in bid order, and bid = x + NBX*y, so ALL pass1 blocks
// (bids 0..679) precede every pass2 block; pass1 blocks never wait ->
// flags always fire -> no deadlock regardless of residency.
__global__ __launch_bounds__(256)
void fused_kernel(const float* __restrict__ in, float* __restrict__ out) {
    int xb = blockIdx.x;
    int pr = xb * 256 + threadIdx.x;
    bool act = (pr < NPAIRS);

    if (blockIdx.y < CH) {
        // ---------------- pass1 role (R12 pass1, verbatim) ----------------
        __shared__ int sflag;
        int c = blockIdx.y;
        const float4* cf = g_ct.c4 + c * LCH;

        if (act) {
            int n  = pr / FC2;
            int fp = pr - n * FC2;
            const float2* xp = (const float2*)in
                             + ((size_t)n * T_LEN + (size_t)c * LCH) * FC2 + fp;
            float Q0=0.f,Q1=0.f,al0=0.f,al1=0.f,be0=0.f,be1=0.f;
#pragma unroll 10
            for (int u = 0; u < LCH; u++) {
                float4 k = cf[u];                // constant cache broadcast
                float2 x = __ldg(xp + (size_t)u * FC2);
                float u0 = x.x - Q0;
                float u1 = x.y - Q1;
                Q0 = fmaf(k.x, u0, Q0);
                Q1 = fmaf(k.x, u1, Q1);
                al0 = fmaf(k.y, al0, (k.z * u0) * u0);
                al1 = fmaf(k.y, al1, (k.z * u1) * u1);
                be0 = fmaf(k.y, be0, k.w * u0);
                be1 = fmaf(k.y, be1, k.w * u1);
            }
            int idx = c * NSER + pr * 2;
            *(float2*)&g_q [idx] = make_float2(Q0, Q1);
            *(float2*)&g_al[idx] = make_float2(al0, al1);
            *(float2*)&g_be[idx] = make_float2(be0, be1);
        }

        // Arrive: one acq_rel atomic per block publishes the block's stores.
        __syncthreads();
        if (threadIdx.x == 0) {
            int old;
            asm volatile("atom.add.acq_rel.gpu.global.s32 %0, [%1], 1;"
                         : "=r"(old) : "l"(&g_cnt[xb]) : "memory");
            sflag = (old == CH - 1);
        }
        __syncthreads();
        if (!sflag) return;

        // Last-arriving block of this x-slice runs the combine.
        if (act) {
            float v20=0.f, v21=0.f, S0=0.f, S1=0.f;
#pragma unroll 8
            for (int k = 0; k < CH; k++) {
                int idx = k * NSER + pr * 2;
                float2 pg = g_ct.ck[k];          // (P, gamma)
                float2 q  = __ldcg((const float2*)&g_q [idx]);
                float2 al = __ldcg((const float2*)&g_al[idx]);
                float2 be = __ldcg((const float2*)&g_be[idx]);
                *(float2*)&g_v2[idx] = make_float2(v20, v21);
                *(float2*)&g_s [idx] = make_float2(S0, S1);
                // S' = P*S + al + v2*(gamma*v2 - 2*be);  v2' = P*v2 + Q
                float c0 = fmaf(pg.y, v20, -2.0f * be.x);
                float c1 = fmaf(pg.y, v21, -2.0f * be.y);
                S0 = fmaf(pg.x, S0, fmaf(v20, c0, al.x));
                S1 = fmaf(pg.x, S1, fmaf(v21, c1, al.y));
                v20 = fmaf(pg.x, v20, q.x);
                v21 = fmaf(pg.x, v21, q.y);
            }
        }
        // Publish: all combine stores done -> release slice flag; self-reset.
        __syncthreads();
        if (threadIdx.x == 0) {
            g_cnt[xb] = 0;
            st_rel(&g_done[xb], 1);
        }
    } else {
        // ---------------- pass2 role (R12 pass2 + one-hop wait) -----------
        int c = blockIdx.y - CH;
        const float4* cf = g_ct.c4 + c * LCH;

        // Single-hop wait: slice combine done?
        if (threadIdx.x == 0) {
            while (ld_acq(&g_done[xb]) == 0) { __nanosleep(256); }
        }
        __syncthreads();

        if (act) {
            int n  = pr / FC2;
            int fp = pr - n * FC2;
            size_t base = ((size_t)n * T_LEN + (size_t)c * LCH) * FC2 + fp;
            const float2* xp = (const float2*)in  + base;
            float2*       yp = (float2*)out + base;

            int idx = c * NSER + pr * 2;
            float2 v2 = __ldcg((const float2*)&g_v2[idx]);
            float2 S  = __ldcg((const float2*)&g_s [idx]);
            float v20 = v2.x, v21 = v2.y, S0 = S.x, S1 = S.y;

#pragma unroll 10
            for (int u = 0; u < LCH; u++) {
                float4 k = cf[u];                // constant cache broadcast
                float2 x = __ldg(xp + (size_t)u * FC2);
                float d0 = x.x - v20;
                float d1 = x.y - v21;
                v20 = fmaf(k.x, d0, v20);
                v21 = fmaf(k.x, d1, v21);
                S0 = fmaf(k.y, S0, (k.z * d0) * d0);
                S1 = fmaf(k.y, S1, (k.z * d1) * d1);
                float r0 = rsqrtf(fmaxf(S0, 0.0f) + 1e-5f);
                float r1 = rsqrtf(fmaxf(S1, 0.0f) + 1e-5f);
                float2 y;
                y.x = (k.y * d0) * r0;
                y.y = (k.y * d1) * r1;
                __stcs(yp + (size_t)u * FC2, y);
            }
        }

        // Reader accounting: last pass2 block of the slice resets the flags.
        if (threadIdx.x == 0) {
            int old = atomicAdd(&g_rcnt[xb], 1);
            if (old == CH - 1) {
                g_rcnt[xb] = 0;
                g_done[xb] = 0;
            }
        }
    }
}

// Static host-side coefficient table: stays valid across graph replays.
static CoefTab h_ct;

static void fill_coefs_host() {
    const double b  = (double)0.99f;
    const double c1 = (double)(1.0f - 0.99f);   // exact (Sterbenz)
    for (int t = 0; t < T_LEN; t++) {
        int u  = t % LCH;
        int t0 = t - u;
        double bt1 = pow(b, (double)(t + 1));
        double w   = c1 / (1.0 - bt1);          // w_0 == 1 exactly
        double a   = 1.0 - w;
        double bb  = w * a;
        double Ppre = (u == 0) ? 1.0
                    : pow(b, (double)u) * (1.0 - pow(b, (double)t0))
                      / (1.0 - pow(b, (double)t));
        h_ct.c4[t] = make_float4((float)w, (float)a, (float)bb,
                                 (float)(bb * Ppre));
    }
    for (int c = 0; c < CH; c++) {
        int t0 = c * LCH;
        double ratio = (1.0 - pow(b, (double)t0))
                     / (1.0 - pow(b, (double)(t0 + LCH)));
        double P     = pow(b, (double)LCH) * ratio;   // 0 for chunk 0
        double ga    = (c == 0) ? 0.0
                     : (P / pow(b, (double)t0)) * (1.0 - ratio);
        h_ct.ck[c] = make_float2((float)P, (float)ga);
    }
}

extern "C" void kernel_launch(void* const* d_in, const int* in_sizes, int n_in,
                              void* d_out, int out_size) {
    const float* s = (const float*)d_in[0];
    float* out = (float*)d_out;
    fill_coefs_host();   // same values every call -> deterministic
    cudaMemcpyToSymbolAsync(g_ct, &h_ct, sizeof(CoefTab), 0,
                            cudaMemcpyHostToDevice);
    fused_kernel<<<dim3(NBX, 2 * CH), 256>>>(s, out);   // (17, 80)
}